// round 2
// baseline (speedup 1.0000x reference)
#include <cuda_runtime.h>
#include <cstdint>

#define N_IDX 4096

// Per-index bilinear metadata for levels f1/f2/f3 (f0 is identity gather).
// 16 bytes -> one LDG.128 per sample point.
struct __align__(16) Meta {
    int   p00;  // y0c*W + x0c (clamped top-left tap, linear offset in plane)
    int   d;    // (dyRow << 16) | dxCol   where dyRow = (y1c-y0c)*W, dxCol = x1c-x0c
    float wy;
    float wx;
};

__device__ Meta g_meta[3 * N_IDX];

__global__ void precompute_meta(const int* __restrict__ indices) {
    int t = blockIdx.x * blockDim.x + threadIdx.x;
    if (t >= 3 * N_IDX) return;
    int lvl = t / N_IDX;        // 0 -> f1 (128), 1 -> f2 (64), 2 -> f3 (32)
    int j   = t - lvl * N_IDX;
    int H   = 128 >> lvl;       // square planes
    float scale = (float)H * (1.0f / 256.0f);

    int idx = indices[j];
    int iy = idx >> 8;
    int ix = idx & 255;
    // half-pixel centers (align_corners=False); upsample => triangle kernel,
    // clamped edge taps are exactly equivalent to jax's edge handling.
    float sy = ((float)iy + 0.5f) * scale - 0.5f;
    float sx = ((float)ix + 0.5f) * scale - 0.5f;
    float y0f = floorf(sy), x0f = floorf(sx);
    float wy = sy - y0f,    wx = sx - x0f;
    int y0 = (int)y0f, x0 = (int)x0f;
    int y0c = min(max(y0,     0), H - 1);
    int y1c = min(max(y0 + 1, 0), H - 1);
    int x0c = min(max(x0,     0), H - 1);
    int x1c = min(max(x0 + 1, 0), H - 1);

    Meta m;
    m.p00 = y0c * H + x0c;
    m.d   = (((y1c - y0c) * H) << 16) | (x1c - x0c);
    m.wy  = wy;
    m.wx  = wx;
    g_meta[t] = m;
}

// f0: identity gather. One CTA per (b, c) plane; coalesced writes, L1-cached
// index reads, scattered LDG reads (only 1.05M loads total -> cheap).
__global__ void gather_f0(const float* __restrict__ f0,
                          const int*   __restrict__ indices,
                          float*       __restrict__ out) {
    int b = blockIdx.x >> 6;          // /64
    int c = blockIdx.x & 63;
    const float* plane = f0 + (size_t)(b * 64 + c) * 65536;
    float*       o     = out + (size_t)(b * 960 + c) * N_IDX;
    for (int j = threadIdx.x; j < N_IDX; j += blockDim.x)
        o[j] = __ldg(plane + __ldg(indices + j));
}

// f1/f2: one CTA per (b, c) plane. Plane is staged in shared memory with a
// single coalesced float4 sweep, then the 4096 random bilinear gathers hit
// smem instead of generating L1tex wavefront storms. Writes are coalesced.
template <int HW, int LVL, int C, int CH_OFF>
__global__ void gather_lvl(const float* __restrict__ f,
                           float*       __restrict__ out) {
    extern __shared__ float s[];
    int b = blockIdx.x / C;
    int c = blockIdx.x - b * C;

    const float4* plane4 = (const float4*)(f + (size_t)(b * C + c) * HW);
    float4* s4 = (float4*)s;
    #pragma unroll 4
    for (int i = threadIdx.x; i < HW / 4; i += blockDim.x)
        s4[i] = plane4[i];
    __syncthreads();

    const int4* meta = (const int4*)(g_meta + LVL * N_IDX);
    float* o = out + (size_t)(b * 960 + CH_OFF + c) * N_IDX;

    for (int j = threadIdx.x; j < N_IDX; j += blockDim.x) {
        int4 mr = __ldg(meta + j);
        int   p00 = mr.x;
        int   dy  = mr.y >> 16;
        int   dx  = mr.y & 0xffff;
        float wy  = __int_as_float(mr.z);
        float wx  = __int_as_float(mr.w);

        float v00 = s[p00];
        float v01 = s[p00 + dx];
        float v10 = s[p00 + dy];
        float v11 = s[p00 + dy + dx];

        float top = v00 + wx * (v01 - v00);
        float bot = v10 + wx * (v11 - v10);
        o[j] = top + wy * (bot - top);
    }
}

// f3: plane is only 4 KB, so one CTA stages CPB=4 channels (16 KB smem) and
// reuses each per-j Meta register load across all 4 channels (4x less meta
// traffic, 4x fewer CTAs).
template <int HW, int LVL, int C, int CH_OFF, int CPB>
__global__ void gather_lvl_multi(const float* __restrict__ f,
                                 float*       __restrict__ out) {
    extern __shared__ float s[];
    int planes = C / CPB;                  // channel-groups per batch
    int b  = blockIdx.x / planes;
    int cg = blockIdx.x - b * planes;
    int c0 = cg * CPB;

    const float4* src4 = (const float4*)(f + (size_t)(b * C + c0) * HW);
    float4* s4 = (float4*)s;
    #pragma unroll 4
    for (int i = threadIdx.x; i < CPB * HW / 4; i += blockDim.x)
        s4[i] = src4[i];
    __syncthreads();

    const int4* meta = (const int4*)(g_meta + LVL * N_IDX);
    float* o = out + (size_t)(b * 960 + CH_OFF + c0) * N_IDX;

    for (int j = threadIdx.x; j < N_IDX; j += blockDim.x) {
        int4 mr = __ldg(meta + j);
        int   p00 = mr.x;
        int   dy  = mr.y >> 16;
        int   dx  = mr.y & 0xffff;
        float wy  = __int_as_float(mr.z);
        float wx  = __int_as_float(mr.w);

        #pragma unroll
        for (int cc = 0; cc < CPB; cc++) {
            const float* sp = s + cc * HW;
            float v00 = sp[p00];
            float v01 = sp[p00 + dx];
            float v10 = sp[p00 + dy];
            float v11 = sp[p00 + dy + dx];
            float top = v00 + wx * (v01 - v00);
            float bot = v10 + wx * (v11 - v10);
            o[cc * N_IDX + j] = top + wy * (bot - top);
        }
    }
}

extern "C" void kernel_launch(void* const* d_in, const int* in_sizes, int n_in,
                              void* d_out, int out_size) {
    // Identify inputs by element count (all distinct); fall back to position.
    const float* f0 = nullptr; const float* f1 = nullptr;
    const float* f2 = nullptr; const float* f3 = nullptr;
    const int* indices = nullptr;
    for (int i = 0; i < n_in; i++) {
        switch (in_sizes[i]) {
            case 16777216: f0 = (const float*)d_in[i]; break;  // 4*64*256*256
            case 8388608:  f1 = (const float*)d_in[i]; break;  // 4*128*128*128
            case 4194304:  f2 = (const float*)d_in[i]; break;  // 4*256*64*64
            case 2097152:  f3 = (const float*)d_in[i]; break;  // 4*512*32*32
            case N_IDX:    indices = (const int*)d_in[i]; break;
        }
    }
    if (!f0 || !f1 || !f2 || !f3 || !indices) {
        f0 = (const float*)d_in[0];
        f1 = (const float*)d_in[1];
        f2 = (const float*)d_in[2];
        f3 = (const float*)d_in[3];
        indices = (const int*)d_in[4];
    }
    float* out = (float*)d_out;

    // Opt in to >48KB dynamic smem (idempotent host-side call, capture-legal).
    cudaFuncSetAttribute(gather_lvl<16384, 0, 128, 64>,
                         cudaFuncAttributeMaxDynamicSharedMemorySize, 65536);

    precompute_meta<<<(3 * N_IDX + 255) / 256, 256>>>(indices);

    gather_f0<<<4 * 64, 256>>>(f0, indices, out);

    gather_lvl<16384, 0, 128,  64><<<4 * 128, 256, 65536>>>(f1, out);
    gather_lvl< 4096, 1, 256, 192><<<4 * 256, 256, 16384>>>(f2, out);
    gather_lvl_multi<1024, 2, 512, 448, 4><<<4 * 128, 256, 16384>>>(f3, out);
}